// round 17
// baseline (speedup 1.0000x reference)
#include <cuda_runtime.h>
#include <cstdint>

// ---------------------------------------------------------------------------
// SSDTargetGenerator for GB300.  R17 = resubmit of unbenched R16 (broker
// timeout). From R15's measured 178.7us:
//  * k_zero launched unconditionally (rotates the fixed ncu -s window off
//    k_out to reveal the ~100us unexplained constant; suspect: k_select's
//    100-block under-occupancy streaming 48MB).
//  * k_select: per-warp-bounded radix scans + 1 barrier/bit via s_tot[32].
//  * k_greedy: 2 barriers/iter via double-buffered s_best[2].
//  * k_iou/k_out unchanged (validated bit-exact; rel_err 4.4e-8).
// No global atomics. No cross-launch state. Graph-capturable.
// ---------------------------------------------------------------------------

#define MAXM    128     // max gt boxes
#define TOPK    128     // per-column survivor list (> M-1 removals)
#define MAXN    131072  // max anchors (N=120000)
#define SEGS    8       // warps per k_select block
#define SEGCAP  2048    // per-warp segment capacity (expected ~990)
#define WIN     (SEGS * SEGCAP)   // 16384-slot window (64KB dynamic smem)
#define BATCH   8       // values loaded per thread before ballot rounds

__device__ float g_iou_mat[(size_t)MAXM * MAXN];   // column-major [c*N + i]
__device__ int   g_cr[MAXM][WIN];                  // per-column compacted rows
__device__ float g_top_iou[MAXM][TOPK];
__device__ int   g_top_row[MAXM][TOPK];
__device__ int   g_top_cnt[MAXM];
__device__ int   g_match[MAXN];

// ---------------------------------------------------------------- k_zero ----
// Zeroes [zero_from, out_size); launched unconditionally (empty when equal)
// to shift the ncu capture window onto a different kernel.
__global__ void k_zero(float* __restrict__ out, int zero_from, int out_size) {
    int stride = gridDim.x * blockDim.x;
    for (int i = zero_from + blockIdx.x * blockDim.x + threadIdx.x;
         i < out_size; i += stride)
        out[i] = 0.0f;
}

// ----------------------------------------------------------------- k_iou ----
// Per anchor: IoU vs all M gt boxes. Per-anchor argmax (first-occurrence ==
// jnp.argmax) for MaximumMatcher. Dense column-major store (coalesced): value
// if iou > 1e-12 (bipartite threshold) else 0. No atomics.
__global__ void k_iou(const float4* __restrict__ anchors,
                      const float4* __restrict__ gt,
                      int N, int M) {
    __shared__ float4 s_gt[MAXM];
    __shared__ float  s_area[MAXM];
    for (int c = threadIdx.x; c < M; c += blockDim.x) {
        float4 g = gt[c];
        s_gt[c] = g;
        s_area[c] = (g.z - g.x) * (g.w - g.y);
    }
    __syncthreads();

    const int i = blockIdx.x * blockDim.x + threadIdx.x;
    if (i >= N || i >= MAXN) return;

    float4 a = anchors[i];                     // center format (cx,cy,w,h)
    float hw = a.z * 0.5f, hh = a.w * 0.5f;
    float ax1 = a.x - hw, ay1 = a.y - hh;
    float ax2 = a.x + hw, ay2 = a.y + hh;
    float area_a = (ax2 - ax1) * (ay2 - ay1);  // replicate reference op order

    float best = 0.0f;
    int   argc = 0;
    float* __restrict__ outp = g_iou_mat + i;

    #pragma unroll 4
    for (int c = 0; c < M; ++c) {
        float4 g = s_gt[c];
        float tlx = fmaxf(ax1, g.x), tly = fmaxf(ay1, g.y);
        float brx = fminf(ax2, g.z), bry = fminf(ay2, g.w);
        float wx = brx - tlx, wy = bry - tly;

        float val = 0.0f;
        if (wx > 0.0f && wy > 0.0f) {
            float inter = wx * wy;
            float iou = inter / (area_a + s_area[c] - inter);   // IEEE div == ref
            if (iou > best) { best = iou; argc = c; }           // first-occurrence
            if (iou > 1e-12f) val = iou;
        }
        outp[(size_t)c * N] = val;
    }
    g_match[i] = (best >= 0.5f) ? argc : -1;   // MaximumMatcher
}

// -------------------------------------------------------------- k_select ----
// One block (256 thr = 8 warps) per column. Dynamic shared = 64KB value window.
// Phase 1: batched compaction (MLP=8 loads, ballot+popc, values->shared,
// rows->global). Phase 2: exact radix top-128 with per-warp-bounded scans
// (each warp scans only its own wcnt entries) and 1 barrier per bit; then
// gather >T, ==T smallest rows, rank-sort (iou desc, row asc) == argmax order.
__global__ void k_select(int N, int M) {
    extern __shared__ float s_val[];            // WIN floats (64KB)
    const int c    = blockIdx.x;
    const int tid  = threadIdx.x;
    const int wid  = tid >> 5;
    const int lane = tid & 31;

    const float* __restrict__ col = g_iou_mat + (size_t)c * N;
    int* __restrict__ cr = g_cr[c];

    __shared__ int   s_cnt[SEGS];
    __shared__ int   s_tot[32];                 // per-bit count accumulators
    __shared__ int   s_pos;
    __shared__ int   s_eqn;
    __shared__ int   s_eqrows[256];
    __shared__ float s_v[TOPK];
    __shared__ int   s_r[TOPK];

    // ---- Phase 1: batched warp-segmented compaction ----
    const int wbase = wid * SEGCAP;
    int woff = 0;                               // warp-uniform running offset
    for (int base = 0; base < N; base += 256 * BATCH) {
        float v[BATCH];
        #pragma unroll
        for (int k = 0; k < BATCH; ++k) {
            int i = base + k * 256 + tid;
            v[k] = (i < N) ? col[i] : 0.0f;     // independent loads, MLP=BATCH
        }
        #pragma unroll
        for (int k = 0; k < BATCH; ++k) {
            unsigned m = __ballot_sync(0xFFFFFFFFu, v[k] > 0.0f);
            if (v[k] > 0.0f) {
                int p = woff + __popc(m & ((1u << lane) - 1u));
                if (p < SEGCAP) {
                    s_val[wbase + p] = v[k];
                    cr[wbase + p]    = base + k * 256 + tid;
                }
            }
            woff += __popc(m);
        }
    }
    const int wcnt = woff < SEGCAP ? woff : SEGCAP;
    if (lane == 0) s_cnt[wid] = wcnt;
    if (tid < 32) s_tot[tid] = 0;               // pre-zero radix accumulators
    if (tid == 0) { s_pos = 0; s_eqn = 0; }
    __syncthreads();

    int n_total = 0;
    #pragma unroll
    for (int w = 0; w < SEGS; ++w) n_total += s_cnt[w];

    const int K = n_total < TOPK ? n_total : TOPK;
    if (K == 0) { if (tid == 0) g_top_cnt[c] = 0; return; }

    // ---- Phase 2: radix threshold T = K-th largest (bit 29 down; IoU <= 1).
    // Per-warp-bounded scans: warp w scans only its own wcnt entries.
    unsigned prefix = 0u;
    for (int b = 29; b >= 0; --b) {
        unsigned test = prefix | (1u << b);
        int local = 0;
        for (int i = lane; i < wcnt; i += 32)
            local += (__float_as_uint(s_val[wbase + i]) >= test) ? 1 : 0;
        #pragma unroll
        for (int s = 16; s > 0; s >>= 1)
            local += __shfl_down_sync(0xFFFFFFFFu, local, s);
        if (lane == 0) atomicAdd(&s_tot[b], local);
        __syncthreads();                        // one barrier per bit
        if (s_tot[b] >= K) prefix = test;       // uniform decision
    }
    const unsigned T = prefix;                  // T > 0 since K <= n_total

    // ---- Gather strictly-greater (unordered; rank-sorted below) ----
    for (int i = lane; i < wcnt; i += 32) {
        if (__float_as_uint(s_val[wbase + i]) > T) {
            int p = atomicAdd(&s_pos, 1);       // shared, < 128 total
            if (p < TOPK) {
                g_top_iou[c][p] = s_val[wbase + i];
                g_top_row[c][p] = cr[wbase + i];
            }
        }
    }
    __syncthreads();
    const int cnt_gt = s_pos < TOPK ? s_pos : TOPK;
    const int need   = K - cnt_gt;              // >= 1 by construction of T

    // ---- Entries equal to T: keep 'need' smallest rows (argmax tie order) ----
    for (int i = lane; i < wcnt; i += 32) {
        if (__float_as_uint(s_val[wbase + i]) == T) {
            int p = atomicAdd(&s_eqn, 1);
            if (p < 256) s_eqrows[p] = cr[wbase + i];
        }
    }
    __syncthreads();
    const int eqn = s_eqn < 256 ? s_eqn : 256;
    if (tid < eqn) {
        int r = s_eqrows[tid];
        int rank = 0;
        for (int j = 0; j < eqn; ++j) rank += (s_eqrows[j] < r) ? 1 : 0;
        if (rank < need && (cnt_gt + rank) < TOPK) {
            g_top_iou[c][cnt_gt + rank] = __uint_as_float(T);
            g_top_row[c][cnt_gt + rank] = r;
        }
    }
    __syncthreads();

    // ---- Rank-sort K entries: iou desc, row asc on ties ----
    if (tid < K) { s_v[tid] = g_top_iou[c][tid]; s_r[tid] = g_top_row[c][tid]; }
    __syncthreads();
    if (tid < K) {
        float v = s_v[tid]; int r = s_r[tid];
        int rank = 0;
        for (int j = 0; j < K; ++j) {
            float vj = s_v[j]; int rj = s_r[j];
            rank += ((vj > v) || (vj == v && rj < r)) ? 1 : 0;
        }
        if (rank < TOPK) {
            g_top_iou[c][rank] = v;
            g_top_row[c][rank] = r;
        }
    }
    if (tid == 0) g_top_cnt[c] = K;
}

// -------------------------------------------------------------- k_greedy ----
// Single block, 128 threads, M iterations, all-LDS after coalesced preload.
// Double-buffered s_best[2] -> 2 barriers/iteration. Key packing unchanged:
// (iou_bits << 25) | (2^25-1 - (r*M+c)); max == (iou desc, flat asc) == argmax.
__global__ void k_greedy(int N, int M) {
    extern __shared__ unsigned char s_dyn[];
    float* s_tv = (float*)s_dyn;                         // M*TOPK floats
    int*   s_tr = (int*)(s_dyn + (size_t)M * TOPK * 4);  // M*TOPK ints

    __shared__ unsigned s_removed[MAXN / 32];   // 16 KB bitmap
    __shared__ unsigned char s_matched[128];
    __shared__ unsigned long long s_best[2];

    const int tid = threadIdx.x;
    for (int i = tid; i < MAXN / 32; i += 128) s_removed[i] = 0;
    s_matched[tid] = 0;
    if (tid < 2) s_best[tid] = 0ull;

    for (int idx = tid; idx < M * TOPK; idx += 128) {
        int cc = idx / TOPK, kk = idx % TOPK;
        s_tv[idx] = g_top_iou[cc][kk];
        s_tr[idx] = g_top_row[cc][kk];
    }

    int ptr = 0;
    const int cnt = (tid < M) ? g_top_cnt[tid] : 0;
    __syncthreads();

    for (int it = 0; it < M; ++it) {
        const int p = it & 1;
        unsigned long long key = 0ull;
        if (tid < M && !s_matched[tid]) {
            while (ptr < cnt) {
                int row = s_tr[tid * TOPK + ptr];
                if (s_removed[row >> 5] & (1u << (row & 31))) { ++ptr; continue; }
                unsigned vb = __float_as_uint(s_tv[tid * TOPK + ptr]);
                unsigned flat = (unsigned)row * (unsigned)M + (unsigned)tid;
                key = ((unsigned long long)vb << 25) |
                      (unsigned long long)(0x1FFFFFFu - flat);
                break;
            }
        }
        if (key) atomicMax(&s_best[p], key);
        __syncthreads();                        // barrier 1: all arrivals in

        unsigned long long b = s_best[p];
        if (b == 0ull) break;                   // uniform: no candidates left

        unsigned flat = 0x1FFFFFFu - (unsigned)(b & 0x1FFFFFFu);
        int bc = (int)(flat % (unsigned)M);
        int br = (int)(flat / (unsigned)M);

        if (tid == 0) {
            s_best[p] = 0ull;                   // recycle slot for it+2
            s_removed[br >> 5] |= 1u << (br & 31);
            if (br < MAXN) g_match[br] = bc;    // bipartite overrides max-match
        }
        if (tid == bc) s_matched[tid] = 1;
        __syncthreads();                        // barrier 2: bitmap visible
    }
}

// ----------------------------------------------------------------- k_out ----
// Layout [cls(N) | box(4N) | mask(N)] = 6N (validated, bit-exact):
// cls at out[i]; box at out[N+4i..+3]; mask scalar at out[5N+i].
__global__ void k_out(const float4* __restrict__ anchors,
                      const float4* __restrict__ gt,
                      const int* __restrict__ gt_ids,
                      int N, int M, float* __restrict__ out, int out_size) {
    int i = blockIdx.x * blockDim.x + threadIdx.x;
    if (i >= N || i >= MAXN) return;

    int m = g_match[i];
    if (m >= M) m = -1;
    const bool pos = (m >= 0);

    float cls_v = 0.0f;
    float t0 = 0.0f, t1 = 0.0f, t2 = 0.0f, t3 = 0.0f, mk = 0.0f;

    if (pos) {
        cls_v = (float)gt_ids[m] + 1.0f;
        mk = 1.0f;

        float4 g = gt[m];                        // corner format
        float gw = g.z - g.x, gh = g.w - g.y;
        float gcx = g.x + 0.5f * gw, gcy = g.y + 0.5f * gh;

        float4 a = anchors[i];                   // center format
        float hw = a.z * 0.5f, hh = a.w * 0.5f;
        float ax1 = a.x - hw, ay1 = a.y - hh;
        float ax2 = a.x + hw, ay2 = a.y + hh;
        float aw = ax2 - ax1, ah = ay2 - ay1;
        float acx = ax1 + 0.5f * aw, acy = ay1 + 0.5f * ah;

        t0 = (gcx - acx) / aw / 0.1f;
        t1 = (gcy - acy) / ah / 0.1f;
        t2 = logf(gw / aw) / 0.2f;
        t3 = logf(gh / ah) / 0.2f;
    }

    if (i < out_size) out[i] = cls_v;

    int b0 = N + 4 * i;
    if (b0 + 3 < out_size) {
        *(float4*)(out + b0) = make_float4(t0, t1, t2, t3);
    } else {
        if (b0 + 0 < out_size) out[b0 + 0] = t0;
        if (b0 + 1 < out_size) out[b0 + 1] = t1;
        if (b0 + 2 < out_size) out[b0 + 2] = t2;
        if (b0 + 3 < out_size) out[b0 + 3] = t3;
    }

    int m0 = 5 * N + i;
    if (m0 < out_size) out[m0] = mk;
}

// ---------------------------------------------------------------------------
extern "C" void kernel_launch(void* const* d_in, const int* in_sizes, int n_in,
                              void* d_out, int out_size) {
    const float4* anchors = (const float4*)d_in[0];   // (N,4) center format
    const float4* gt      = (const float4*)d_in[1];   // (M,4) corner format
    const int*    gt_ids  = (const int*)d_in[2];      // (M,1) int32

    int N = in_sizes[0] / 4;
    int M = in_sizes[1] / 4;
    if (N > MAXN) N = MAXN;
    if (M > MAXM) M = MAXM;
    float* out = (float*)d_out;

    // Host-side attribute sets: idempotent, not stream ops, capture-safe.
    cudaFuncSetAttribute(k_select,
        cudaFuncAttributeMaxDynamicSharedMemorySize, WIN * 4);
    cudaFuncSetAttribute(k_greedy,
        cudaFuncAttributeMaxDynamicSharedMemorySize, MAXM * TOPK * 8);

    // Always launch (empty when out_size <= 6N) — shifts the ncu -s window so
    // the captured kernel rotates off k_out and reveals an unknown.
    int zero_from = (out_size > 6 * N) ? 6 * N : out_size;
    int tail = out_size - zero_from;
    int zgrid = tail > 0 ? (tail + 255) / 256 : 1;
    if (zgrid > 1184) zgrid = 1184;
    k_zero<<<zgrid, 256>>>(out, zero_from, out_size);

    k_iou<<<(N + 255) / 256, 256>>>(anchors, gt, N, M);
    k_select<<<M, 256, WIN * 4>>>(N, M);
    k_greedy<<<1, 128, (size_t)M * TOPK * 8>>>(N, M);
    k_out<<<(N + 255) / 256, 256>>>(anchors, gt, gt_ids, N, M, out, out_size);
}